// round 6
// baseline (speedup 1.0000x reference)
#include <cuda_runtime.h>

// FKPositionLoss: B=256, J=24, T=1024, F=8 sampled frames.
// Loss = mean over (B,F,J,3) of (pred_pos - target_pos)^2.
// Root translation cancels (identical additive term on both sides).
//
// Two-kernel split:
//   K1: one thread per (item, side, joint): 6-float strided gather + 6d->quat,
//       coalesced float4 store to scratch. ~40 regs -> high occupancy -> the
//       scattered-sector gather runs at the l1tex wavefront floor.
//   K2: one thread per (item, side): register-resident FK chain; pred/target
//       diff via __shfl_xor with the paired lane; block reduce + self-resetting
//       global accumulator (graph-replay deterministic).

#define NB 256
#define NJ 24
#define NT 1024
#define NF 8
#define NITEMS (NB * NF)                 // 2048 (b,f) items
#define DENOM2 294912.0                  // 2 * B*F*J*3 (each pair counted twice)

#define K1_THREADS 256
#define K1_TOTAL (NITEMS * 2 * NJ)       // 98304 threads
#define K1_GRID (K1_TOTAL / K1_THREADS)  // 384

#define K2_THREADS 128
#define K2_TOTAL (NITEMS * 2)            // 4096 threads (item, side)
#define K2_GRID (K2_TOTAL / K2_THREADS)  // 32

// Scratch: local quats for all (item, side, joint). 98304 * 16B = 1.5 MB.
__device__ float4 g_quat[K1_TOTAL];

// Self-resetting accumulator (zero at load; reset by final K2 block each launch).
__device__ double g_sum;
__device__ unsigned int g_count;

// jnp.linspace(0, 1023, 8).astype(int32)
__constant__ int c_tidx[NF] = {0, 146, 292, 438, 584, 730, 876, 1023};

// ---------------------------------------------------------------------------
// Kernel 1: gather + 6d -> rotation matrix -> quaternion
// ---------------------------------------------------------------------------
__global__ __launch_bounds__(K1_THREADS) void gather_quat_kernel(
    const float* __restrict__ pred,
    const float* __restrict__ targ)
{
    const int idx = blockIdx.x * K1_THREADS + threadIdx.x;
    // idx = item*48 + side*24 + j
    const int j    = idx % NJ;
    const int side = (idx / NJ) & 1;
    const int item = idx / (2 * NJ);
    const int b    = item >> 3;
    const int f    = item & 7;

    const float* __restrict__ src = side ? targ : pred;
    const long base = ((long)(b * NJ + j) * 6) * NT + c_tidx[f];

    const float r0 = __ldg(src + base + 0 * NT);
    const float r1 = __ldg(src + base + 1 * NT);
    const float r2 = __ldg(src + base + 2 * NT);
    const float r3 = __ldg(src + base + 3 * NT);
    const float r4 = __ldg(src + base + 4 * NT);
    const float r5 = __ldg(src + base + 5 * NT);

    // Gram-Schmidt (Zhou et al.): rows b1, b2, b3 = b1 x b2
    const float n1   = sqrtf(r0 * r0 + r1 * r1 + r2 * r2);
    const float inv1 = 1.0f / fmaxf(n1, 1e-8f);
    const float b1x = r0 * inv1, b1y = r1 * inv1, b1z = r2 * inv1;

    const float d  = b1x * r3 + b1y * r4 + b1z * r5;
    const float ux = r3 - d * b1x, uy = r4 - d * b1y, uz = r5 - d * b1z;
    const float n2   = sqrtf(ux * ux + uy * uy + uz * uz);
    const float inv2 = 1.0f / fmaxf(n2, 1e-8f);
    const float b2x = ux * inv2, b2y = uy * inv2, b2z = uz * inv2;

    const float b3x = b1y * b2z - b1z * b2y;
    const float b3y = b1z * b2x - b1x * b2z;
    const float b3z = b1x * b2y - b1y * b2x;

    const float m00 = b1x, m01 = b1y, m02 = b1z;
    const float m10 = b2x, m11 = b2y, m12 = b2z;
    const float m20 = b3x, m21 = b3y, m22 = b3z;

    // matrix -> quaternion (pytorch3d-style; argmax candidate, lowest index
    // wins ties, matching jnp.argmax)
    const float q0 = sqrtf(fmaxf(1.0f + m00 + m11 + m22, 0.0f));
    const float q1 = sqrtf(fmaxf(1.0f + m00 - m11 - m22, 0.0f));
    const float q2 = sqrtf(fmaxf(1.0f - m00 + m11 - m22, 0.0f));
    const float q3 = sqrtf(fmaxf(1.0f - m00 - m11 + m22, 0.0f));

    int best = 0; float bq = q0;
    if (q1 > bq) { bq = q1; best = 1; }
    if (q2 > bq) { bq = q2; best = 2; }
    if (q3 > bq) { bq = q3; best = 3; }
    const float s = 0.5f / fmaxf(bq, 0.1f);

    float qw, qx, qy, qz;
    if (best == 0)      { qw = q0 * q0;  qx = m21 - m12; qy = m02 - m20; qz = m10 - m01; }
    else if (best == 1) { qw = m21 - m12; qx = q1 * q1;  qy = m10 + m01; qz = m02 + m20; }
    else if (best == 2) { qw = m02 - m20; qx = m10 + m01; qy = q2 * q2;  qz = m12 + m21; }
    else                { qw = m10 - m01; qx = m20 + m02; qy = m21 + m12; qz = q3 * q3;  }

    g_quat[idx] = make_float4(qw * s, qx * s, qy * s, qz * s);
}

// ---------------------------------------------------------------------------
// Kernel 2: forward kinematics (one side per thread, paired lanes) + loss
// ---------------------------------------------------------------------------
__global__ __launch_bounds__(K2_THREADS) void fk_loss_kernel(
    const float* __restrict__ offsets,
    float* __restrict__ out)
{
    __shared__ float wsum[K2_THREADS / 32];

    const int tid = threadIdx.x;
    const int gid = blockIdx.x * K2_THREADS + tid;
    // gid = item*2 + side; lanes (2k, 2k+1) form a pred/target pair.

    float gw[NJ], gx[NJ], gy[NJ], gz[NJ];
    float px[NJ], py[NJ], pz[NJ];
    const int par[NJ] = {-1, 0, 0, 0, 1, 2, 3, 4, 5, 6, 7, 8,
                          9, 9, 9, 12, 13, 14, 16, 17, 18, 19, 20, 21};

    const float4* __restrict__ q = &g_quat[gid * NJ];

    float acc = 0.0f;
#pragma unroll
    for (int j = 0; j < NJ; j++) {
        const float4 lq = q[j];
        if (par[j] < 0) {
            gw[j] = lq.x; gx[j] = lq.y; gy[j] = lq.z; gz[j] = lq.w;
            px[j] = 0.0f; py[j] = 0.0f; pz[j] = 0.0f;  // root translation cancels
        } else {
            const int p = par[j];
            const float w1 = gw[p], x1 = gx[p], y1 = gy[p], z1 = gz[p];
            const float w2 = lq.x, x2 = lq.y, y2 = lq.z, z2 = lq.w;
            gw[j] = w1 * w2 - x1 * x2 - y1 * y2 - z1 * z2;
            gx[j] = w1 * x2 + x1 * w2 + y1 * z2 - z1 * y2;
            gy[j] = w1 * y2 - x1 * z2 + y1 * w2 + z1 * x2;
            gz[j] = w1 * z2 + x1 * y2 - y1 * x2 + z1 * w2;

            const float vx = __ldg(offsets + j * 3 + 0);
            const float vy = __ldg(offsets + j * 3 + 1);
            const float vz = __ldg(offsets + j * 3 + 2);
            const float tx = 2.0f * (y1 * vz - z1 * vy);
            const float ty = 2.0f * (z1 * vx - x1 * vz);
            const float tz = 2.0f * (x1 * vy - y1 * vx);
            px[j] = px[p] + vx + w1 * tx + (y1 * tz - z1 * ty);
            py[j] = py[p] + vy + w1 * ty + (z1 * tx - x1 * tz);
            pz[j] = pz[p] + vz + w1 * tz + (x1 * ty - y1 * tx);

            // diff vs paired lane (other side); both lanes add the same dd^2,
            // so the final denominator is doubled (DENOM2).
            const float dx = px[j] - __shfl_xor_sync(0xffffffffu, px[j], 1);
            const float dy = py[j] - __shfl_xor_sync(0xffffffffu, py[j], 1);
            const float dz = pz[j] - __shfl_xor_sync(0xffffffffu, pz[j], 1);
            acc += dx * dx + dy * dy + dz * dz;
        }
    }

    // warp + block reduce
#pragma unroll
    for (int off = 16; off > 0; off >>= 1)
        acc += __shfl_down_sync(0xffffffffu, acc, off);
    if ((tid & 31) == 0) wsum[tid >> 5] = acc;
    __syncthreads();

    if (tid == 0) {
        double blocksum = 0.0;
#pragma unroll
        for (int w = 0; w < K2_THREADS / 32; w++) blocksum += (double)wsum[w];
        atomicAdd(&g_sum, blocksum);
        __threadfence();
        const unsigned int old = atomicAdd(&g_count, 1u);
        if (old == K2_GRID - 1) {
            const double tot = atomicAdd(&g_sum, 0.0);  // atomic read after all adds
            out[0] = (float)(tot / DENOM2);
            g_sum = 0.0;            // reset for next graph replay
            __threadfence();
            g_count = 0u;
        }
    }
}

extern "C" void kernel_launch(void* const* d_in, const int* in_sizes, int n_in,
                              void* d_out, int out_size)
{
    // Inputs (metadata order): pred_rot_6d, target_rot_6d, root_translation, offsets.
    // Selected defensively by element count; root_translation unused (cancels in MSE).
    const float* pred = nullptr;
    const float* targ = nullptr;
    const float* offsets = nullptr;
    const int big = NB * NJ * 6 * NT;  // 37,748,736
    for (int i = 0; i < n_in; i++) {
        if (in_sizes[i] == big) {
            if (!pred) pred = (const float*)d_in[i];
            else if (!targ) targ = (const float*)d_in[i];
        } else if (in_sizes[i] == NJ * 3) {
            offsets = (const float*)d_in[i];
        }
    }
    gather_quat_kernel<<<K1_GRID, K1_THREADS>>>(pred, targ);
    fk_loss_kernel<<<K2_GRID, K2_THREADS>>>(offsets, (float*)d_out);
}

// round 7
// speedup vs baseline: 1.1373x; 1.1373x over previous
#include <cuda_runtime.h>

// FKPositionLoss: B=256, J=24, T=1024, F=8 sampled frames.
// Loss = mean over (B,F,J,3) of (pred_pos - target_pos)^2.
// Root translation cancels (identical additive term on both sides).
//
// Single fused kernel, one thread per (item, side, joint) = 98304 threads.
// FK is computed per-joint via the ancestor-path product (max depth 8), reading
// ancestor local quats from shared memory — same left-to-right association as
// the reference recurrence, so rounding matches exactly. This removes the
// 9.6us MLP-starved scratch-readback kernel seen in the R6 profile.

#define NB 256
#define NJ 24
#define NT 1024
#define NF 8
#define NITEMS (NB * NF)            // 2048 (b,f) items
#define DENOM 147456.0              // B*F*J*3

#define IPB 4                       // items per block
#define NTHREADS (IPB * 2 * NJ)     // 192
#define NGRID (NITEMS / IPB)        // 512
#define MAXD 8                      // max ancestor-path length (root-exclusive)

// Self-resetting accumulator (zero at load; reset by final block each launch
// -> deterministic under CUDA-graph replay).
__device__ double g_sum;
__device__ unsigned int g_count;

// jnp.linspace(0, 1023, 8).astype(int32)
__constant__ int c_tidx[NF] = {0, 146, 292, 438, 584, 730, 876, 1023};

// Root-exclusive ancestor path per joint, packed 5 bits/node (value = node+1,
// 0 = none), ordered root-side first. PARENTS = (-1,0,0,0,1,2,3,4,5,6,7,8,
// 9,9,9,12,13,14,16,17,18,19,20,21).
__constant__ unsigned long long c_path[NJ] = {
    0ULL,                                        // j0 (root)
    2ULL,                                        // j1: [1]
    3ULL,                                        // j2: [2]
    4ULL,                                        // j3: [3]
    2ULL | (5ULL << 5),                          // j4: [1,4]
    3ULL | (6ULL << 5),                          // j5: [2,5]
    4ULL | (7ULL << 5),                          // j6: [3,6]
    2ULL | (5ULL << 5) | (8ULL << 10),           // j7: [1,4,7]
    3ULL | (6ULL << 5) | (9ULL << 10),           // j8: [2,5,8]
    4ULL | (7ULL << 5) | (10ULL << 10),          // j9: [3,6,9]
    2ULL | (5ULL << 5) | (8ULL << 10) | (11ULL << 15),   // j10: [1,4,7,10]
    3ULL | (6ULL << 5) | (9ULL << 10) | (12ULL << 15),   // j11: [2,5,8,11]
    4ULL | (7ULL << 5) | (10ULL << 10) | (13ULL << 15),  // j12: [3,6,9,12]
    4ULL | (7ULL << 5) | (10ULL << 10) | (14ULL << 15),  // j13: [3,6,9,13]
    4ULL | (7ULL << 5) | (10ULL << 10) | (15ULL << 15),  // j14: [3,6,9,14]
    4ULL | (7ULL << 5) | (10ULL << 10) | (13ULL << 15) | (16ULL << 20),  // j15
    4ULL | (7ULL << 5) | (10ULL << 10) | (14ULL << 15) | (17ULL << 20),  // j16
    4ULL | (7ULL << 5) | (10ULL << 10) | (15ULL << 15) | (18ULL << 20),  // j17
    4ULL | (7ULL << 5) | (10ULL << 10) | (14ULL << 15) | (17ULL << 20) | (19ULL << 25),  // j18
    4ULL | (7ULL << 5) | (10ULL << 10) | (15ULL << 15) | (18ULL << 20) | (20ULL << 25),  // j19
    4ULL | (7ULL << 5) | (10ULL << 10) | (14ULL << 15) | (17ULL << 20) | (19ULL << 25) | (21ULL << 30),  // j20
    4ULL | (7ULL << 5) | (10ULL << 10) | (15ULL << 15) | (18ULL << 20) | (20ULL << 25) | (22ULL << 30),  // j21
    4ULL | (7ULL << 5) | (10ULL << 10) | (14ULL << 15) | (17ULL << 20) | (19ULL << 25) | (21ULL << 30) | (23ULL << 35),  // j22
    4ULL | (7ULL << 5) | (10ULL << 10) | (15ULL << 15) | (18ULL << 20) | (20ULL << 25) | (22ULL << 30) | (24ULL << 35),  // j23
};

__global__ __launch_bounds__(NTHREADS) void fk_loss_fused_kernel(
    const float* __restrict__ pred,
    const float* __restrict__ targ,
    const float* __restrict__ offsets,
    float* __restrict__ out)
{
    __shared__ float4 qsh[IPB][2][NJ];     // local quats (w,x,y,z)
    __shared__ float  psm[IPB][NJ][3];     // target-side positions
    __shared__ float  offs[NJ * 3];
    __shared__ float  wsum[NTHREADS / 32];

    const int tid    = threadIdx.x;
    const int item_l = tid / 48;
    const int r      = tid - item_l * 48;
    const int side   = r / NJ;
    const int j      = r - side * NJ;
    const int item   = blockIdx.x * IPB + item_l;
    const int b      = item >> 3;
    const int f      = item & 7;

    if (tid < NJ * 3) offs[tid] = offsets[tid];

    // ---- phase 1: gather 6 floats, 6d -> rotation matrix -> quaternion ----
    {
        const float* __restrict__ src = side ? targ : pred;
        const long base = ((long)(b * NJ + j) * 6) * NT + c_tidx[f];

        const float r0 = __ldg(src + base + 0 * NT);
        const float r1 = __ldg(src + base + 1 * NT);
        const float r2 = __ldg(src + base + 2 * NT);
        const float r3 = __ldg(src + base + 3 * NT);
        const float r4 = __ldg(src + base + 4 * NT);
        const float r5 = __ldg(src + base + 5 * NT);

        // Gram-Schmidt (Zhou et al.): rows b1, b2, b3 = b1 x b2
        const float n1   = sqrtf(r0 * r0 + r1 * r1 + r2 * r2);
        const float inv1 = 1.0f / fmaxf(n1, 1e-8f);
        const float b1x = r0 * inv1, b1y = r1 * inv1, b1z = r2 * inv1;

        const float d  = b1x * r3 + b1y * r4 + b1z * r5;
        const float ux = r3 - d * b1x, uy = r4 - d * b1y, uz = r5 - d * b1z;
        const float n2   = sqrtf(ux * ux + uy * uy + uz * uz);
        const float inv2 = 1.0f / fmaxf(n2, 1e-8f);
        const float b2x = ux * inv2, b2y = uy * inv2, b2z = uz * inv2;

        const float b3x = b1y * b2z - b1z * b2y;
        const float b3y = b1z * b2x - b1x * b2z;
        const float b3z = b1x * b2y - b1y * b2x;

        const float m00 = b1x, m01 = b1y, m02 = b1z;
        const float m10 = b2x, m11 = b2y, m12 = b2z;
        const float m20 = b3x, m21 = b3y, m22 = b3z;

        // matrix -> quaternion (pytorch3d-style; argmax candidate, lowest index
        // wins ties, matching jnp.argmax)
        const float q0 = sqrtf(fmaxf(1.0f + m00 + m11 + m22, 0.0f));
        const float q1 = sqrtf(fmaxf(1.0f + m00 - m11 - m22, 0.0f));
        const float q2 = sqrtf(fmaxf(1.0f - m00 + m11 - m22, 0.0f));
        const float q3 = sqrtf(fmaxf(1.0f - m00 - m11 + m22, 0.0f));

        int best = 0; float bq = q0;
        if (q1 > bq) { bq = q1; best = 1; }
        if (q2 > bq) { bq = q2; best = 2; }
        if (q3 > bq) { bq = q3; best = 3; }
        const float s = 0.5f / fmaxf(bq, 0.1f);

        float qw, qx, qy, qz;
        if (best == 0)      { qw = q0 * q0;  qx = m21 - m12; qy = m02 - m20; qz = m10 - m01; }
        else if (best == 1) { qw = m21 - m12; qx = q1 * q1;  qy = m10 + m01; qz = m02 + m20; }
        else if (best == 2) { qw = m02 - m20; qx = m10 + m01; qy = q2 * q2;  qz = m12 + m21; }
        else                { qw = m10 - m01; qx = m20 + m02; qy = m21 + m12; qz = q3 * q3;  }

        qsh[item_l][side][j] = make_float4(qw * s, qx * s, qy * s, qz * s);
    }
    __syncthreads();

    // ---- phase 2: per-joint FK via ancestor-path walk (depth <= 8) ----
    // Recurrence (identical association to reference):
    //   gq = lq[0]; pos = 0;
    //   for node a along path: pos += rotate(gq, off[a]); gq = gq * lq[a];
    float px = 0.0f, py = 0.0f, pz = 0.0f;
    {
        const float4 lq0 = qsh[item_l][side][0];
        float gw = lq0.x, gx = lq0.y, gy = lq0.z, gz = lq0.w;

        unsigned long long pp = c_path[j];
#pragma unroll
        for (int step = 0; step < MAXD; step++) {
            const int a = (int)(pp & 31ULL) - 1;
            pp >>= 5;
            if (a >= 0) {
                const float vx = offs[a * 3 + 0];
                const float vy = offs[a * 3 + 1];
                const float vz = offs[a * 3 + 2];
                // pos += quat_rotate(gq, v)
                const float tx = 2.0f * (gy * vz - gz * vy);
                const float ty = 2.0f * (gz * vx - gx * vz);
                const float tz = 2.0f * (gx * vy - gy * vx);
                px += vx + gw * tx + (gy * tz - gz * ty);
                py += vy + gw * ty + (gz * tx - gx * tz);
                pz += vz + gw * tz + (gx * ty - gy * tx);
                // gq = gq * lq[a]
                const float4 la = qsh[item_l][side][a];
                const float w2 = la.x, x2 = la.y, y2 = la.z, z2 = la.w;
                const float nw = gw * w2 - gx * x2 - gy * y2 - gz * z2;
                const float nx = gw * x2 + gx * w2 + gy * z2 - gz * y2;
                const float ny = gw * y2 - gx * z2 + gy * w2 + gz * x2;
                const float nz = gw * z2 + gx * y2 - gy * x2 + gz * w2;
                gw = nw; gx = nx; gy = ny; gz = nz;
            }
        }
    }

    // ---- phase 3: pred/target diff + reduction ----
    if (side == 1) {
        psm[item_l][j][0] = px;
        psm[item_l][j][1] = py;
        psm[item_l][j][2] = pz;
    }
    __syncthreads();

    float acc = 0.0f;
    if (side == 0) {
        const float dx = px - psm[item_l][j][0];
        const float dy = py - psm[item_l][j][1];
        const float dz = pz - psm[item_l][j][2];
        acc = dx * dx + dy * dy + dz * dz;
    }

#pragma unroll
    for (int off = 16; off > 0; off >>= 1)
        acc += __shfl_down_sync(0xffffffffu, acc, off);
    if ((tid & 31) == 0) wsum[tid >> 5] = acc;
    __syncthreads();

    if (tid == 0) {
        double blocksum = 0.0;
#pragma unroll
        for (int w = 0; w < NTHREADS / 32; w++) blocksum += (double)wsum[w];
        atomicAdd(&g_sum, blocksum);
        __threadfence();
        const unsigned int old = atomicAdd(&g_count, 1u);
        if (old == NGRID - 1) {
            const double tot = atomicAdd(&g_sum, 0.0);  // atomic read after all adds
            out[0] = (float)(tot / DENOM);
            g_sum = 0.0;            // reset for next graph replay
            __threadfence();
            g_count = 0u;
        }
    }
}

extern "C" void kernel_launch(void* const* d_in, const int* in_sizes, int n_in,
                              void* d_out, int out_size)
{
    // Inputs (metadata order): pred_rot_6d, target_rot_6d, root_translation, offsets.
    // Selected defensively by element count; root_translation unused (cancels in MSE).
    const float* pred = nullptr;
    const float* targ = nullptr;
    const float* offsets = nullptr;
    const int big = NB * NJ * 6 * NT;  // 37,748,736
    for (int i = 0; i < n_in; i++) {
        if (in_sizes[i] == big) {
            if (!pred) pred = (const float*)d_in[i];
            else if (!targ) targ = (const float*)d_in[i];
        } else if (in_sizes[i] == NJ * 3) {
            offsets = (const float*)d_in[i];
        }
    }
    fk_loss_fused_kernel<<<NGRID, NTHREADS>>>(pred, targ, offsets, (float*)d_out);
}

// round 9
// speedup vs baseline: 1.1629x; 1.0226x over previous
#include <cuda_runtime.h>

// FKPositionLoss: B=256, J=24, T=1024, F=8 sampled frames.
// Loss = mean over (B,F,J,3) of (pred_pos - target_pos)^2.
// Root translation cancels (identical additive term on both sides).
//
// Single fused kernel; TWO threads per (item, side, joint) = 196608 threads.
// Each thread of a pair gathers 3 of the 6 rotation floats (keeps per-thread
// MLP at 3 while doubling warp count vs R7 -> occupancy 29% -> ~65%), the
// halves are exchanged with one __shfl_xor, and the quat conversion runs
// redundantly in both lanes (ALU is idle). FK via compile-time ancestor-path
// walk (max depth 8) as in R7 (rel_err was 0.0).

#define NB 256
#define NJ 24
#define NT 1024
#define NF 8
#define NITEMS (NB * NF)            // 2048 (b,f) items
#define DENOM 147456.0              // B*F*J*3

#define IPB 2                       // items per block
#define NTHREADS (IPB * 2 * NJ * 2) // 192 (2 threads per rotation)
#define NGRID (NITEMS / IPB)        // 1024
#define MAXD 8                      // max ancestor-path length (root-exclusive)

// Self-resetting accumulator (zero at load; reset by final block each launch
// -> deterministic under CUDA-graph replay).
__device__ double g_sum;
__device__ unsigned int g_count;

// jnp.linspace(0, 1023, 8).astype(int32)
__constant__ int c_tidx[NF] = {0, 146, 292, 438, 584, 730, 876, 1023};

// Root-exclusive ancestor path per joint, packed 5 bits/node (value = node+1,
// 0 = none), root-side first. PARENTS = (-1,0,0,0,1,2,3,4,5,6,7,8,
// 9,9,9,12,13,14,16,17,18,19,20,21).
__constant__ unsigned long long c_path[NJ] = {
    0ULL,
    2ULL,
    3ULL,
    4ULL,
    2ULL | (5ULL << 5),
    3ULL | (6ULL << 5),
    4ULL | (7ULL << 5),
    2ULL | (5ULL << 5) | (8ULL << 10),
    3ULL | (6ULL << 5) | (9ULL << 10),
    4ULL | (7ULL << 5) | (10ULL << 10),
    2ULL | (5ULL << 5) | (8ULL << 10) | (11ULL << 15),
    3ULL | (6ULL << 5) | (9ULL << 10) | (12ULL << 15),
    4ULL | (7ULL << 5) | (10ULL << 10) | (13ULL << 15),
    4ULL | (7ULL << 5) | (10ULL << 10) | (14ULL << 15),
    4ULL | (7ULL << 5) | (10ULL << 10) | (15ULL << 15),
    4ULL | (7ULL << 5) | (10ULL << 10) | (13ULL << 15) | (16ULL << 20),
    4ULL | (7ULL << 5) | (10ULL << 10) | (14ULL << 15) | (17ULL << 20),
    4ULL | (7ULL << 5) | (10ULL << 10) | (15ULL << 15) | (18ULL << 20),
    4ULL | (7ULL << 5) | (10ULL << 10) | (14ULL << 15) | (17ULL << 20) | (19ULL << 25),
    4ULL | (7ULL << 5) | (10ULL << 10) | (15ULL << 15) | (18ULL << 20) | (20ULL << 25),
    4ULL | (7ULL << 5) | (10ULL << 10) | (14ULL << 15) | (17ULL << 20) | (19ULL << 25) | (21ULL << 30),
    4ULL | (7ULL << 5) | (10ULL << 10) | (15ULL << 15) | (18ULL << 20) | (20ULL << 25) | (22ULL << 30),
    4ULL | (7ULL << 5) | (10ULL << 10) | (14ULL << 15) | (17ULL << 20) | (19ULL << 25) | (21ULL << 30) | (23ULL << 35),
    4ULL | (7ULL << 5) | (10ULL << 10) | (15ULL << 15) | (18ULL << 20) | (20ULL << 25) | (22ULL << 30) | (24ULL << 35),
};

__global__ __launch_bounds__(NTHREADS) void fk_loss_fused_kernel(
    const float* __restrict__ pred,
    const float* __restrict__ targ,
    const float* __restrict__ offsets,
    float* __restrict__ out)
{
    __shared__ float4 qsh[IPB][2][NJ];     // local quats (w,x,y,z)
    __shared__ float  psm[IPB][NJ][3];     // target-side positions
    __shared__ float  offs[NJ * 3];
    __shared__ float  wsum[NTHREADS / 32];

    const int tid = threadIdx.x;

    if (tid < NJ * 3) offs[tid] = offsets[tid];

    // ---- phase 1: paired gather (3 floats each) + 6d -> quat ----
    {
        const int h      = tid & 1;          // half within the pair
        const int pair   = tid >> 1;         // 0..95
        const int item_l = pair / (2 * NJ);
        const int r      = pair - item_l * (2 * NJ);
        const int side   = r / NJ;
        const int j      = r - side * NJ;
        const int item   = blockIdx.x * IPB + item_l;
        const int b      = item >> 3;
        const int f      = item & 7;

        const float* __restrict__ src = side ? targ : pred;
        const long base = ((long)(b * NJ + j) * 6) * NT + c_tidx[f]
                          + (long)h * 3 * NT;

        // this lane's 3 components (h=0: r0..r2, h=1: r3..r5)
        const float a0 = __ldg(src + base + 0 * NT);
        const float a1 = __ldg(src + base + 1 * NT);
        const float a2 = __ldg(src + base + 2 * NT);

        // exchange with the paired adjacent lane
        const float p0 = __shfl_xor_sync(0xffffffffu, a0, 1);
        const float p1 = __shfl_xor_sync(0xffffffffu, a1, 1);
        const float p2 = __shfl_xor_sync(0xffffffffu, a2, 1);

        const float r0 = h ? p0 : a0;
        const float r1 = h ? p1 : a1;
        const float r2 = h ? p2 : a2;
        const float r3 = h ? a0 : p0;
        const float r4 = h ? a1 : p1;
        const float r5 = h ? a2 : p2;

        // Gram-Schmidt (Zhou et al.): rows b1, b2, b3 = b1 x b2
        const float n1   = sqrtf(r0 * r0 + r1 * r1 + r2 * r2);
        const float inv1 = 1.0f / fmaxf(n1, 1e-8f);
        const float b1x = r0 * inv1, b1y = r1 * inv1, b1z = r2 * inv1;

        const float d  = b1x * r3 + b1y * r4 + b1z * r5;
        const float ux = r3 - d * b1x, uy = r4 - d * b1y, uz = r5 - d * b1z;
        const float n2   = sqrtf(ux * ux + uy * uy + uz * uz);
        const float inv2 = 1.0f / fmaxf(n2, 1e-8f);
        const float b2x = ux * inv2, b2y = uy * inv2, b2z = uz * inv2;

        const float b3x = b1y * b2z - b1z * b2y;
        const float b3y = b1z * b2x - b1x * b2z;
        const float b3z = b1x * b2y - b1y * b2x;

        const float m00 = b1x, m01 = b1y, m02 = b1z;
        const float m10 = b2x, m11 = b2y, m12 = b2z;
        const float m20 = b3x, m21 = b3y, m22 = b3z;

        // matrix -> quaternion (pytorch3d-style; argmax candidate, lowest index
        // wins ties, matching jnp.argmax)
        const float q0 = sqrtf(fmaxf(1.0f + m00 + m11 + m22, 0.0f));
        const float q1 = sqrtf(fmaxf(1.0f + m00 - m11 - m22, 0.0f));
        const float q2 = sqrtf(fmaxf(1.0f - m00 + m11 - m22, 0.0f));
        const float q3 = sqrtf(fmaxf(1.0f - m00 - m11 + m22, 0.0f));

        int best = 0; float bq = q0;
        if (q1 > bq) { bq = q1; best = 1; }
        if (q2 > bq) { bq = q2; best = 2; }
        if (q3 > bq) { bq = q3; best = 3; }
        const float s = 0.5f / fmaxf(bq, 0.1f);

        float qw, qx, qy, qz;
        if (best == 0)      { qw = q0 * q0;  qx = m21 - m12; qy = m02 - m20; qz = m10 - m01; }
        else if (best == 1) { qw = m21 - m12; qx = q1 * q1;  qy = m10 + m01; qz = m02 + m20; }
        else if (best == 2) { qw = m02 - m20; qx = m10 + m01; qy = q2 * q2;  qz = m12 + m21; }
        else                { qw = m10 - m01; qx = m20 + m02; qy = m21 + m12; qz = q3 * q3;  }

        if (h == 0)
            qsh[item_l][side][j] = make_float4(qw * s, qx * s, qy * s, qz * s);
    }
    __syncthreads();

    // ---- phase 2: per-joint FK via ancestor-path walk (depth <= 8) ----
    // Threads 0..95: one per (item_l, side, joint). Recurrence (identical
    // association to reference): gq = lq[0]; pos = 0;
    //   for node a along path: pos += rotate(gq, off[a]); gq = gq * lq[a];
    float px = 0.0f, py = 0.0f, pz = 0.0f;
    int fk_item = 0, fk_side = 0, fk_j = 0;
    const bool fk_active = tid < IPB * 2 * NJ;
    if (fk_active) {
        fk_item = tid / (2 * NJ);
        const int r2 = tid - fk_item * (2 * NJ);
        fk_side = r2 / NJ;
        fk_j    = r2 - fk_side * NJ;

        const float4 lq0 = qsh[fk_item][fk_side][0];
        float gw = lq0.x, gx = lq0.y, gy = lq0.z, gz = lq0.w;

        unsigned long long pp = c_path[fk_j];
#pragma unroll
        for (int step = 0; step < MAXD; step++) {
            const int a = (int)(pp & 31ULL) - 1;
            pp >>= 5;
            if (a >= 0) {
                const float vx = offs[a * 3 + 0];
                const float vy = offs[a * 3 + 1];
                const float vz = offs[a * 3 + 2];
                // pos += quat_rotate(gq, v)
                const float tx = 2.0f * (gy * vz - gz * vy);
                const float ty = 2.0f * (gz * vx - gx * vz);
                const float tz = 2.0f * (gx * vy - gy * vx);
                px += vx + gw * tx + (gy * tz - gz * ty);
                py += vy + gw * ty + (gz * tx - gx * tz);
                pz += vz + gw * tz + (gx * ty - gy * tx);
                // gq = gq * lq[a]
                const float4 la = qsh[fk_item][fk_side][a];
                const float w2 = la.x, x2 = la.y, y2 = la.z, z2 = la.w;
                const float nw = gw * w2 - gx * x2 - gy * y2 - gz * z2;
                const float nx = gw * x2 + gx * w2 + gy * z2 - gz * y2;
                const float ny = gw * y2 - gx * z2 + gy * w2 + gz * x2;
                const float nz = gw * z2 + gx * y2 - gy * x2 + gz * w2;
                gw = nw; gx = nx; gy = ny; gz = nz;
            }
        }

        if (fk_side == 1) {
            psm[fk_item][fk_j][0] = px;
            psm[fk_item][fk_j][1] = py;
            psm[fk_item][fk_j][2] = pz;
        }
    }
    __syncthreads();

    // ---- phase 3: pred/target diff + reduction ----
    float acc = 0.0f;
    if (fk_active && fk_side == 0) {
        const float dx = px - psm[fk_item][fk_j][0];
        const float dy = py - psm[fk_item][fk_j][1];
        const float dz = pz - psm[fk_item][fk_j][2];
        acc = dx * dx + dy * dy + dz * dz;
    }

#pragma unroll
    for (int off = 16; off > 0; off >>= 1)
        acc += __shfl_down_sync(0xffffffffu, acc, off);
    if ((tid & 31) == 0) wsum[tid >> 5] = acc;
    __syncthreads();

    if (tid == 0) {
        double blocksum = 0.0;
#pragma unroll
        for (int w = 0; w < NTHREADS / 32; w++) blocksum += (double)wsum[w];
        atomicAdd(&g_sum, blocksum);
        __threadfence();
        const unsigned int old = atomicAdd(&g_count, 1u);
        if (old == NGRID - 1) {
            const double tot = atomicAdd(&g_sum, 0.0);  // atomic read after all adds
            out[0] = (float)(tot / DENOM);
            g_sum = 0.0;            // reset for next graph replay
            __threadfence();
            g_count = 0u;
        }
    }
}

extern "C" void kernel_launch(void* const* d_in, const int* in_sizes, int n_in,
                              void* d_out, int out_size)
{
    // Inputs (metadata order): pred_rot_6d, target_rot_6d, root_translation, offsets.
    // Selected defensively by element count; root_translation unused (cancels in MSE).
    const float* pred = nullptr;
    const float* targ = nullptr;
    const float* offsets = nullptr;
    const int big = NB * NJ * 6 * NT;  // 37,748,736
    for (int i = 0; i < n_in; i++) {
        if (in_sizes[i] == big) {
            if (!pred) pred = (const float*)d_in[i];
            else if (!targ) targ = (const float*)d_in[i];
        } else if (in_sizes[i] == NJ * 3) {
            offsets = (const float*)d_in[i];
        }
    }
    fk_loss_fused_kernel<<<NGRID, NTHREADS>>>(pred, targ, offsets, (float*)d_out);
}